// round 11
// baseline (speedup 1.0000x reference)
#include <cuda_runtime.h>
#include <math.h>

// Problem shape (fixed by dataset): B=32, L=8192, K=64, 20 amino acids.
#define B_DIM 32
#define L_DIM 8192
#define K_DIM 64
#define THREADS 256
#define WARPS (THREADS / 32)
#define ROWS_PER_U  (WARPS * 4)            // 32 rows per u-step
#define CHUNK_ROWS  (ROWS_PER_U * 2)       // 64 rows per chunk
#define N_CHUNKS    (L_DIM / CHUNK_ROWS)   // 128 chunks per batch row
#define BLOCKS_PER_B 23                    // 32 x 23 = 736 blocks = 1 wave @ occ 5
#define CHUNK_STRIDE_ROWS (BLOCKS_PER_B * CHUNK_ROWS)   // 1472

__global__ __launch_bounds__(THREADS, 5)
void hp_pairs_kernel(const int* __restrict__ seq,
                     const float* __restrict__ r,
                     const int* __restrict__ j_idx,
                     const float* __restrict__ h,
                     const float* __restrict__ r_half_raw,
                     const float* __restrict__ tau_hp_raw,
                     const int* __restrict__ max_dist,
                     float* __restrict__ out)
{
    __shared__ float s_hseq[L_DIM];   // h[seq[b, :]] for this batch row (32 KB)

    const int b    = blockIdx.x;
    const int tblk = blockIdx.y;      // 0..22
    const int tid  = threadIdx.x;
    const int lane = tid & 31;
    const int warp = tid >> 5;

    // Each lane holds one h-table entry (20 entries <= 32 lanes).
    const float h_lane = h[min(lane, 19)];

    // Stage h[seq[b,:]] into smem ONCE per block: LDG.128 -> 4x shfl -> STS.128.
    {
        const int4* src = (const int4*)(seq + b * L_DIM);
        float4*     dst = (float4*)s_hseq;
        #pragma unroll
        for (int it = 0; it < L_DIM / 4 / THREADS; ++it) {
            int4 s4 = src[tid + it * THREADS];
            float4 v;
            v.x = __shfl_sync(0xffffffffu, h_lane, s4.x);
            v.y = __shfl_sync(0xffffffffu, h_lane, s4.y);
            v.z = __shfl_sync(0xffffffffu, h_lane, s4.z);
            v.w = __shfl_sync(0xffffffffu, h_lane, s4.w);
            dst[tid + it * THREADS] = v;
        }
    }

    // Scalars. g = exp(-(r-rp)^2/(2 s^2)) = 2^( qa*r^2 + qb*r + qc ), qa<0.
    const float md     = (float)(*max_dist);
    const float r_peak = log1pf(expf(*r_half_raw));
    const float sigma  = log1pf(expf(*tau_hp_raw)) + 0.1f;
    const float qa     = -1.44269504088896340736f / (2.0f * sigma * sigma);
    const float qb     = -2.0f * qa * r_peak;
    const float qc     = qa * r_peak * r_peak;
    const float thresh = md - 1e-4f;

    __syncthreads();

    // Mapping: 8 lanes per row, 4 rows per warp, 32 rows per u-step.
    const int l8   = lane & 7;
    const int rgrp = lane >> 3;
    const int rowoff = warp * 4 + rgrp;

    const int nchunks = (N_CHUNKS - tblk + BLOCKS_PER_B - 1) / BLOCKS_PER_B;
    const int nsteps  = nchunks * 2;            // always even

    // Load-position pointers (advance as we prefetch)
    const int row_base = tblk * CHUNK_ROWS + rowoff;
    const float* rp = r     + ((size_t)b * L_DIM + row_base) * K_DIM + l8 * 4;
    const int*   jp = j_idx + ((size_t)b * L_DIM + row_base) * K_DIM + l8 * 4;
    float*       ob = out   + (size_t)b * L_DIM;

    // Step deltas (in elements): u0->u1 within chunk, u1->u0 of next chunk.
    const size_t d0 = (size_t)ROWS_PER_U * K_DIM;                          // 2048
    const size_t d1 = (size_t)(CHUNK_STRIDE_ROWS - ROWS_PER_U) * K_DIM;    // 92160

    // Double buffers (compile-time parity, no dynamic indexing).
    float4 ra0[2], ra1[2];
    int4   ja0[2], ja1[2];

#define LOADBUF(JA, RA, JP, RP)                         \
    do {                                                \
        (JA)[0] = __ldcs((const int4*)(JP));            \
        (JA)[1] = __ldcs((const int4*)((JP) + 32));     \
        (RA)[0] = __ldcs((const float4*)(RP));          \
        (RA)[1] = __ldcs((const float4*)((RP) + 32));   \
    } while (0)

#define CONSUME(JA, RA, ROW)                                            \
    do {                                                                \
        float hj[8];                                                    \
        hj[0] = s_hseq[(JA)[0].x & (L_DIM - 1)];                        \
        hj[1] = s_hseq[(JA)[0].y & (L_DIM - 1)];                        \
        hj[2] = s_hseq[(JA)[0].z & (L_DIM - 1)];                        \
        hj[3] = s_hseq[(JA)[0].w & (L_DIM - 1)];                        \
        hj[4] = s_hseq[(JA)[1].x & (L_DIM - 1)];                        \
        hj[5] = s_hseq[(JA)[1].y & (L_DIM - 1)];                        \
        hj[6] = s_hseq[(JA)[1].z & (L_DIM - 1)];                        \
        hj[7] = s_hseq[(JA)[1].w & (L_DIM - 1)];                        \
        float rv[8] = { (RA)[0].x, (RA)[0].y, (RA)[0].z, (RA)[0].w,     \
                        (RA)[1].x, (RA)[1].y, (RA)[1].z, (RA)[1].w };   \
        float g[8];                                                     \
        _Pragma("unroll")                                               \
        for (int e = 0; e < 8; ++e) {                                   \
            float t = fmaf(fmaf(qa, rv[e], qb), rv[e], qc);             \
            t = (rv[e] < thresh) ? t : -350.0f;                         \
            asm("ex2.approx.ftz.f32 %0, %1;" : "=f"(g[e]) : "f"(t));    \
        }                                                               \
        float a0 = hj[0] * g[0], a1 = hj[1] * g[1];                     \
        a0 = fmaf(hj[2], g[2], a0);  a1 = fmaf(hj[3], g[3], a1);        \
        a0 = fmaf(hj[4], g[4], a0);  a1 = fmaf(hj[5], g[5], a1);        \
        a0 = fmaf(hj[6], g[6], a0);  a1 = fmaf(hj[7], g[7], a1);        \
        float acc = a0 + a1;                                            \
        acc += __shfl_xor_sync(0xffffffffu, acc, 4);                    \
        acc += __shfl_xor_sync(0xffffffffu, acc, 2);                    \
        acc += __shfl_xor_sync(0xffffffffu, acc, 1);                    \
        if (l8 == 0) ob[(ROW)] = s_hseq[(ROW)] * acc;                   \
    } while (0)

    // Prologue: load step 0 (even), advance to step 1's position.
    LOADBUF(ja0, ra0, jp, rp);
    rp += d0; jp += d0;
    int row_cur = row_base;

    for (int s = 0; s < nsteps; s += 2) {
        // prefetch step s+1 (odd) into buf1; advance to step s+2
        LOADBUF(ja1, ra1, jp, rp);
        rp += d1; jp += d1;

        // consume step s (buf0)
        CONSUME(ja0, ra0, row_cur);
        row_cur += ROWS_PER_U;

        // prefetch step s+2 (even) into buf0; advance to step s+3
        if (s + 2 < nsteps) {
            LOADBUF(ja0, ra0, jp, rp);
            rp += d0; jp += d0;
        }

        // consume step s+1 (buf1)
        CONSUME(ja1, ra1, row_cur);
        row_cur += CHUNK_STRIDE_ROWS - ROWS_PER_U;
    }

#undef LOADBUF
#undef CONSUME
}

extern "C" void kernel_launch(void* const* d_in, const int* in_sizes, int n_in,
                              void* d_out, int out_size)
{
    // metadata order: seq, r, j_idx, h, r_half_raw, tau_hp_raw, max_dist
    const int*   seq        = (const int*)d_in[0];
    const float* r          = (const float*)d_in[1];
    const int*   j_idx      = (const int*)d_in[2];
    const float* h          = (const float*)d_in[3];
    const float* r_half_raw = (const float*)d_in[4];
    const float* tau_hp_raw = (const float*)d_in[5];
    const int*   max_dist   = (const int*)d_in[6];
    float*       out        = (float*)d_out;

    dim3 grid(B_DIM, BLOCKS_PER_B);   // 32 x 23 = 736 blocks = single wave
    hp_pairs_kernel<<<grid, THREADS>>>(seq, r, j_idx, h,
                                       r_half_raw, tau_hp_raw, max_dist, out);
}